// round 1
// baseline (speedup 1.0000x reference)
#include <cuda_runtime.h>
#include <cstdint>

// out[t, d] = sum_{i<4} codebooks[i, d], broadcast to all N tokens.
// (The reference's argmin over a size-1 axis is always 0, so the output is
// input-independent: a single 64-float vector replicated N_TOKENS times.)
//
// Pure DRAM-write-bandwidth kernel: 256 MiB of STG.128 streaming stores.

static constexpr int EMBEDDING_DIM = 64;
static constexpr int VEC4_PER_ROW = EMBEDDING_DIM / 4;  // 16

__global__ void nsvq_broadcast_kernel(const float* __restrict__ codebooks,
                                      float4* __restrict__ out,
                                      size_t n4) {
    const size_t idx    = (size_t)blockIdx.x * blockDim.x + threadIdx.x;
    const size_t stride = (size_t)gridDim.x * blockDim.x;   // multiple of 16 by launch config

    // Position within the 64-float row is loop-invariant because stride % 16 == 0.
    const int vecpos = (int)(idx & (VEC4_PER_ROW - 1));
    const int d = vecpos * 4;

    float4 v;
    v.x = codebooks[d + 0] + codebooks[64 + d + 0] + codebooks[128 + d + 0] + codebooks[192 + d + 0];
    v.y = codebooks[d + 1] + codebooks[64 + d + 1] + codebooks[128 + d + 1] + codebooks[192 + d + 1];
    v.z = codebooks[d + 2] + codebooks[64 + d + 2] + codebooks[128 + d + 2] + codebooks[192 + d + 2];
    v.w = codebooks[d + 3] + codebooks[64 + d + 3] + codebooks[128 + d + 3] + codebooks[192 + d + 3];

    // Streaming 128-bit stores; no reuse, evict-first hint.
    for (size_t i = idx; i < n4; i += stride) {
        __stcs(&out[i], v);
    }
}

extern "C" void kernel_launch(void* const* d_in, const int* in_sizes, int n_in,
                              void* d_out, int out_size) {
    // d_in[0] = input_data (unused — output is input-independent)
    // d_in[1] = codebooks  (1024 x 64 f32; only first 4 rows are used)
    const float* codebooks = (const float*)d_in[1];
    float4* out = (float4*)d_out;

    const size_t n4 = (size_t)out_size / 4;   // 16,777,216 float4 stores

    const int threads = 256;
    const int blocks  = 148 * 16;             // stride = 606208, divisible by 16
    nsvq_broadcast_kernel<<<blocks, threads>>>(codebooks, out, n4);
}